// round 2
// baseline (speedup 1.0000x reference)
#include <cuda_runtime.h>
#include <cuda_bf16.h>

#define NN 50000
#define EE 600000
#define DD 128
#define PITCH 132          // padded transposed-weight pitch (float4-aligned, 2-way write conflicts only)
#define GEMM_ROWS 64
#define GEMM_SMEM ((2*128*PITCH + GEMM_ROWS*128) * 4)

// ---------------- scratch (device globals: no allocation allowed) ----------------
__device__ float g_bufA[NN * DD];
__device__ float g_bufB[NN * DD];
__device__ float g_mean[NN * DD];
__device__ int   g_src[EE];
__device__ int   g_dst[EE];
__device__ int   g_col[EE];
__device__ int   g_rowptr[NN + 1];
__device__ int   g_cursor[NN];
__device__ int   g_count[NN];
__device__ float g_invdeg[NN];
__device__ int   g_is64;

// ---------------- packed f32x2 helpers ----------------
__device__ __forceinline__ unsigned long long pk2(float lo, float hi) {
    unsigned long long r;
    asm("mov.b64 %0, {%1, %2};" : "=l"(r) : "f"(lo), "f"(hi));
    return r;
}
__device__ __forceinline__ void upk2(unsigned long long v, float& lo, float& hi) {
    asm("mov.b64 {%0, %1}, %2;" : "=f"(lo), "=f"(hi) : "l"(v));
}
__device__ __forceinline__ void fma2(unsigned long long& acc, unsigned long long a,
                                     unsigned long long b) {
    asm("fma.rn.f32x2 %0, %1, %2, %0;" : "+l"(acc) : "l"(a), "l"(b));
}

// ---------------- preprocessing ----------------
// Edge dtype detection: reference declares int64 but JAX without x64 emits int32.
// If data is int32, a 64-bit read combines two indices -> almost surely >= NN.
__global__ void detect_kernel(const unsigned long long* __restrict__ e) {
    if (threadIdx.x == 0 && blockIdx.x == 0) {
        int ok = 1;
        #pragma unroll
        for (int i = 0; i < 8; i++)
            if (e[i] >= (unsigned long long)NN) ok = 0;
        g_is64 = ok;
    }
}

__global__ void zero_counts_kernel() {
    int i = blockIdx.x * blockDim.x + threadIdx.x;
    if (i < NN) g_count[i] = 0;
}

__global__ void convert_kernel(const void* __restrict__ eptr) {
    int i = blockIdx.x * blockDim.x + threadIdx.x;
    if (i >= EE) return;
    if (g_is64) {
        const long long* e = (const long long*)eptr;
        g_src[i] = (int)e[i];
        g_dst[i] = (int)e[EE + i];
    } else {
        const int* e = (const int*)eptr;
        g_src[i] = e[i];
        g_dst[i] = e[EE + i];
    }
}

__global__ void hist_kernel() {
    int i = blockIdx.x * blockDim.x + threadIdx.x;
    if (i < EE) atomicAdd(&g_count[g_dst[i]], 1);
}

// Single-block exclusive scan over g_count -> g_rowptr / g_cursor, plus inv-degree.
__global__ void scan_kernel() {
    __shared__ int wsum[32];
    __shared__ int carry_s;
    int tid = threadIdx.x;
    int lane = tid & 31, wid = tid >> 5;
    if (tid == 0) carry_s = 0;
    __syncthreads();
    for (int base = 0; base < NN; base += 1024) {
        int idx = base + tid;
        int v = (idx < NN) ? g_count[idx] : 0;
        int s = v;
        #pragma unroll
        for (int o = 1; o < 32; o <<= 1) {
            int t = __shfl_up_sync(0xffffffffu, s, o);
            if (lane >= o) s += t;
        }
        if (lane == 31) wsum[wid] = s;
        __syncthreads();
        if (wid == 0) {
            int w = wsum[lane];
            #pragma unroll
            for (int o = 1; o < 32; o <<= 1) {
                int t = __shfl_up_sync(0xffffffffu, w, o);
                if (lane >= o) w += t;
            }
            wsum[lane] = w;
        }
        __syncthreads();
        int offset = ((wid > 0) ? wsum[wid - 1] : 0) + carry_s;
        int incl = s + offset;
        if (idx < NN) {
            int excl = incl - v;
            g_rowptr[idx] = excl;
            g_cursor[idx] = excl;
            g_invdeg[idx] = 1.0f / (float)max(v, 1);
        }
        __syncthreads();
        if (tid == 1023) carry_s = incl;
        __syncthreads();
    }
    if (tid == 0) g_rowptr[NN] = carry_s;
}

__global__ void fill_kernel() {
    int i = blockIdx.x * blockDim.x + threadIdx.x;
    if (i >= EE) return;
    int d = g_dst[i];
    int p = atomicAdd(&g_cursor[d], 1);
    g_col[p] = g_src[i];
}

// Sort each adjacency list so float summation order is deterministic across calls
// (atomic fill order is not). Avg degree 12 -> O(deg^2) selection sort is cheap.
__global__ void sortnb_kernel() {
    int n = blockIdx.x * blockDim.x + threadIdx.x;
    if (n >= NN) return;
    int b = g_rowptr[n], e = g_rowptr[n + 1];
    for (int i = b; i < e - 1; i++) {
        int m = i, vm = g_col[i];
        for (int j = i + 1; j < e; j++) {
            int vj = g_col[j];
            if (vj < vm) { m = j; vm = vj; }
        }
        if (m != i) { g_col[m] = g_col[i]; g_col[i] = vm; }
    }
}

// ---------------- per-layer kernels ----------------
// One warp per node; lane owns 4 consecutive floats (float4). Feature table is
// 25.6 MB -> L2-resident, so gathers run at LTS bandwidth, no atomics needed.
__global__ void aggregate_kernel(const float* __restrict__ hin, float* __restrict__ mean) {
    int warp = (blockIdx.x * blockDim.x + threadIdx.x) >> 5;
    if (warp >= NN) return;
    int lane = threadIdx.x & 31;
    int beg = g_rowptr[warp], end = g_rowptr[warp + 1];
    float4 acc = make_float4(0.f, 0.f, 0.f, 0.f);
    for (int j = beg; j < end; j++) {
        int s = g_col[j];
        float4 v = *((const float4*)hin + s * 32 + lane);
        acc.x += v.x; acc.y += v.y; acc.z += v.z; acc.w += v.w;
    }
    float id = g_invdeg[warp];
    acc.x *= id; acc.y *= id; acc.z *= id; acc.w *= id;
    *((float4*)mean + warp * 32 + lane) = acc;
}

// Fused dual GEMM + bias + ReLU: out = relu(mean @ Wl^T + hin @ Wr^T + bl).
// Tile: 64 rows x 128 cols per CTA (256 thr), thread = 4 cols x 8 rows, fp32
// accumulation via packed fma.rn.f32x2 (FFMA2, 2x FFMA issue rate).
__global__ __launch_bounds__(256, 1) void gemm_kernel(
    const float* __restrict__ mean, const float* __restrict__ hin,
    const float* __restrict__ Wl, const float* __restrict__ bl,
    const float* __restrict__ Wr, float* __restrict__ out)
{
    extern __shared__ float sm[];
    float* Wls = sm;                       // [128][PITCH] transposed: Wls[k][n] = Wl[n][k]
    float* Wrs = sm + 128 * PITCH;
    float* xs  = sm + 2 * 128 * PITCH;     // [64][128] row tile

    const int tid = threadIdx.x;
    // Stage both weight matrices transposed (coalesced gmem reads, 2-way smem write conflicts)
    for (int idx = tid; idx < 128 * 32; idx += 256) {
        int n = idx >> 5;
        int k4 = (idx & 31) << 2;
        float4 a = *(const float4*)(Wl + n * 128 + k4);
        Wls[(k4 + 0) * PITCH + n] = a.x; Wls[(k4 + 1) * PITCH + n] = a.y;
        Wls[(k4 + 2) * PITCH + n] = a.z; Wls[(k4 + 3) * PITCH + n] = a.w;
        float4 b = *(const float4*)(Wr + n * 128 + k4);
        Wrs[(k4 + 0) * PITCH + n] = b.x; Wrs[(k4 + 1) * PITCH + n] = b.y;
        Wrs[(k4 + 2) * PITCH + n] = b.z; Wrs[(k4 + 3) * PITCH + n] = b.w;
    }

    const int cg = tid & 31;       // col group: cols [4*cg, 4*cg+4)
    const int rg = tid >> 5;       // row group: rows [8*rg, 8*rg+8)
    const int c0 = cg << 2;
    const int row0 = blockIdx.x * GEMM_ROWS;

    float4 bv = *(const float4*)(bl + c0);
    unsigned long long acc[8][2];
    #pragma unroll
    for (int i = 0; i < 8; i++) { acc[i][0] = pk2(bv.x, bv.y); acc[i][1] = pk2(bv.z, bv.w); }

    #pragma unroll
    for (int ph = 0; ph < 2; ph++) {
        const float* src = ph ? hin : mean;
        const float* Ws  = ph ? Wrs : Wls;
        __syncthreads();   // weights staged (ph0) / previous xs consumed (ph1)
        for (int idx = tid; idx < GEMM_ROWS * 32; idx += 256) {
            int r = idx >> 5;
            int k4 = (idx & 31) << 2;
            int gr = row0 + r;
            float4 v = make_float4(0.f, 0.f, 0.f, 0.f);
            if (gr < NN) v = *(const float4*)(src + gr * 128 + k4);
            *(float4*)(xs + r * 128 + k4) = v;
        }
        __syncthreads();
        const float* xrow = xs + rg * 8 * 128;
        #pragma unroll 4
        for (int k = 0; k < 128; k++) {
            float4 w = *(const float4*)(Ws + k * PITCH + c0);  // conflict-free 512B warp load
            unsigned long long w01 = pk2(w.x, w.y), w23 = pk2(w.z, w.w);
            #pragma unroll
            for (int i = 0; i < 8; i++) {
                float xv = xrow[i * 128 + k];                  // broadcast load
                unsigned long long xx = pk2(xv, xv);
                fma2(acc[i][0], w01, xx);
                fma2(acc[i][1], w23, xx);
            }
        }
    }

    #pragma unroll
    for (int i = 0; i < 8; i++) {
        int gr = row0 + rg * 8 + i;
        if (gr < NN) {
            float a, b, c, d;
            upk2(acc[i][0], a, b);
            upk2(acc[i][1], c, d);
            float4 o = make_float4(fmaxf(a, 0.f), fmaxf(b, 0.f), fmaxf(c, 0.f), fmaxf(d, 0.f));
            *(float4*)(out + gr * 128 + c0) = o;
        }
    }
}

// ---------------- launch ----------------
extern "C" void kernel_launch(void* const* d_in, const int* in_sizes, int n_in,
                              void* d_out, int out_size) {
    const float* x   = (const float*)d_in[0];
    const void*  ei  = d_in[1];
    const float* Wl1 = (const float*)d_in[2];
    const float* bl1 = (const float*)d_in[3];
    const float* Wr1 = (const float*)d_in[4];
    const float* Wl2 = (const float*)d_in[5];
    const float* bl2 = (const float*)d_in[6];
    const float* Wr2 = (const float*)d_in[7];
    const float* Wl3 = (const float*)d_in[8];
    const float* bl3 = (const float*)d_in[9];
    const float* Wr3 = (const float*)d_in[10];
    float* out = (float*)d_out;

    cudaFuncSetAttribute(gemm_kernel, cudaFuncAttributeMaxDynamicSharedMemorySize, GEMM_SMEM);

    float *pA, *pB, *pM;
    cudaGetSymbolAddress((void**)&pA, g_bufA);
    cudaGetSymbolAddress((void**)&pB, g_bufB);
    cudaGetSymbolAddress((void**)&pM, g_mean);

    // ---- graph preprocessing (identical every call: deterministic) ----
    detect_kernel<<<1, 32>>>((const unsigned long long*)ei);
    zero_counts_kernel<<<(NN + 255) / 256, 256>>>();
    convert_kernel<<<(EE + 255) / 256, 256>>>(ei);
    hist_kernel<<<(EE + 255) / 256, 256>>>();
    scan_kernel<<<1, 1024>>>();
    fill_kernel<<<(EE + 255) / 256, 256>>>();
    sortnb_kernel<<<(NN + 127) / 128, 128>>>();

    const int agg_blocks  = (NN * 32 + 255) / 256;        // one warp per node
    const int gemm_blocks = (NN + GEMM_ROWS - 1) / GEMM_ROWS;

    // ---- layer 1 ----
    aggregate_kernel<<<agg_blocks, 256>>>(x, pM);
    gemm_kernel<<<gemm_blocks, 256, GEMM_SMEM>>>(pM, x, Wl1, bl1, Wr1, pA);
    // ---- layer 2 ----
    aggregate_kernel<<<agg_blocks, 256>>>(pA, pM);
    gemm_kernel<<<gemm_blocks, 256, GEMM_SMEM>>>(pM, pA, Wl2, bl2, Wr2, pB);
    // ---- layer 3 ----
    aggregate_kernel<<<agg_blocks, 256>>>(pB, pM);
    gemm_kernel<<<gemm_blocks, 256, GEMM_SMEM>>>(pM, pB, Wl3, bl3, Wr3, out);
}

// round 3
// speedup vs baseline: 1.1921x; 1.1921x over previous
#include <cuda_runtime.h>
#include <cuda_bf16.h>

#define NN 50000
#define EE 600000
#define DD 128
#define PITCH 132          // padded transposed-weight pitch
#define GEMM_ROWS 128
#define GEMM_SMEM ((2*128*PITCH + GEMM_ROWS*128) * 4)

typedef unsigned long long ull;

// ---------------- scratch (device globals: no allocation allowed) ----------------
__device__ float g_bufA[NN * DD];
__device__ float g_bufB[NN * DD];
__device__ float g_mean[NN * DD];
__device__ int   g_src[EE];
__device__ int   g_dst[EE];
__device__ int   g_col[EE];
__device__ int   g_rowptr[NN + 1];
__device__ int   g_cursor[NN];
__device__ int   g_count[NN];
__device__ float g_invdeg[NN];
__device__ int   g_is64;

// ---------------- packed f32x2 helpers ----------------
__device__ __forceinline__ ull pk2(float lo, float hi) {
    ull r;
    asm("mov.b64 %0, {%1, %2};" : "=l"(r) : "f"(lo), "f"(hi));
    return r;
}
__device__ __forceinline__ void upk2(ull v, float& lo, float& hi) {
    asm("mov.b64 {%0, %1}, %2;" : "=f"(lo), "=f"(hi) : "l"(v));
}
__device__ __forceinline__ void fma2(ull& acc, ull a, ull b) {
    asm("fma.rn.f32x2 %0, %1, %2, %0;" : "+l"(acc) : "l"(a), "l"(b));
}

// ---------------- preprocessing ----------------
// Zero per-node counters; thread 0 also detects edge dtype (reference says int64
// but JAX w/o x64 emits int32 — an int64 read of int32 data is almost surely >= NN).
__global__ void init_kernel(const unsigned long long* __restrict__ e) {
    int i = blockIdx.x * blockDim.x + threadIdx.x;
    if (i < NN) g_count[i] = 0;
    if (i == 0) {
        int ok = 1;
        #pragma unroll
        for (int t = 0; t < 8; t++)
            if (e[t] >= (unsigned long long)NN) ok = 0;
        g_is64 = ok;
    }
}

// Convert edge list to int32 and histogram dst degrees in one pass.
__global__ void convert_hist_kernel(const void* __restrict__ eptr) {
    int i = blockIdx.x * blockDim.x + threadIdx.x;
    if (i >= EE) return;
    int s, d;
    if (g_is64) {
        const long long* e = (const long long*)eptr;
        s = (int)e[i];
        d = (int)e[EE + i];
    } else {
        const int* e = (const int*)eptr;
        s = e[i];
        d = e[EE + i];
    }
    g_src[i] = s;
    g_dst[i] = d;
    atomicAdd(&g_count[d], 1);
}

// Single-block exclusive scan over g_count -> g_rowptr / g_cursor, plus inv-degree.
__global__ void scan_kernel() {
    __shared__ int wsum[32];
    __shared__ int carry_s;
    int tid = threadIdx.x;
    int lane = tid & 31, wid = tid >> 5;
    if (tid == 0) carry_s = 0;
    __syncthreads();
    for (int base = 0; base < NN; base += 1024) {
        int idx = base + tid;
        int v = (idx < NN) ? g_count[idx] : 0;
        int s = v;
        #pragma unroll
        for (int o = 1; o < 32; o <<= 1) {
            int t = __shfl_up_sync(0xffffffffu, s, o);
            if (lane >= o) s += t;
        }
        if (lane == 31) wsum[wid] = s;
        __syncthreads();
        if (wid == 0) {
            int w = wsum[lane];
            #pragma unroll
            for (int o = 1; o < 32; o <<= 1) {
                int t = __shfl_up_sync(0xffffffffu, w, o);
                if (lane >= o) w += t;
            }
            wsum[lane] = w;
        }
        __syncthreads();
        int offset = ((wid > 0) ? wsum[wid - 1] : 0) + carry_s;
        int incl = s + offset;
        if (idx < NN) {
            int excl = incl - v;
            g_rowptr[idx] = excl;
            g_cursor[idx] = excl;
            g_invdeg[idx] = 1.0f / (float)max(v, 1);
        }
        __syncthreads();
        if (tid == 1023) carry_s = incl;
        __syncthreads();
    }
    if (tid == 0) g_rowptr[NN] = carry_s;
}

__global__ void fill_kernel() {
    int i = blockIdx.x * blockDim.x + threadIdx.x;
    if (i >= EE) return;
    int d = g_dst[i];
    int p = atomicAdd(&g_cursor[d], 1);
    g_col[p] = g_src[i];
}

// Sort each adjacency list so float summation order is deterministic
// (atomic fill order is not). Avg degree 12 -> O(deg^2) selection sort is cheap.
__global__ void sortnb_kernel() {
    int n = blockIdx.x * blockDim.x + threadIdx.x;
    if (n >= NN) return;
    int b = g_rowptr[n], e = g_rowptr[n + 1];
    for (int i = b; i < e - 1; i++) {
        int m = i, vm = g_col[i];
        for (int j = i + 1; j < e; j++) {
            int vj = g_col[j];
            if (vj < vm) { m = j; vm = vj; }
        }
        if (m != i) { g_col[m] = g_col[i]; g_col[i] = vm; }
    }
}

// ---------------- per-layer kernels ----------------
// One warp per node; lane owns a float4. 25.6 MB table is L2-resident.
// Unroll-2 raises MLP; summation order matches sorted sequential order.
__global__ void aggregate_kernel(const float* __restrict__ hin, float* __restrict__ mean) {
    int node = (blockIdx.x * blockDim.x + threadIdx.x) >> 5;
    if (node >= NN) return;
    int lane = threadIdx.x & 31;
    int j = g_rowptr[node], end = g_rowptr[node + 1];
    const float4* p = (const float4*)hin;
    float4 acc = make_float4(0.f, 0.f, 0.f, 0.f);
    for (; j + 2 <= end; j += 2) {
        int s0 = g_col[j], s1 = g_col[j + 1];
        float4 v0 = p[s0 * 32 + lane];
        float4 v1 = p[s1 * 32 + lane];
        acc.x += v0.x; acc.y += v0.y; acc.z += v0.z; acc.w += v0.w;
        acc.x += v1.x; acc.y += v1.y; acc.z += v1.z; acc.w += v1.w;
    }
    if (j < end) {
        float4 v = p[g_col[j] * 32 + lane];
        acc.x += v.x; acc.y += v.y; acc.z += v.z; acc.w += v.w;
    }
    float id = g_invdeg[node];
    acc.x *= id; acc.y *= id; acc.z *= id; acc.w *= id;
    *((float4*)mean + node * 32 + lane) = acc;
}

// Fused dual GEMM + bias + ReLU: out = relu(mean @ Wl^T + hin @ Wr^T + bl).
// CTA tile 128x128, 256 threads, thread tile 8 rows x 8 cols (cols 4*lc and 64+4*lc).
// x rows xor-4 swizzled in smem so the warp's two row-groups hit disjoint banks.
// Packed fma.rn.f32x2 accumulation; x prefetched 4 k-steps ahead for ILP.
__global__ __launch_bounds__(256, 1) void gemm_kernel(
    const float* __restrict__ mean, const float* __restrict__ hin,
    const float* __restrict__ Wl, const float* __restrict__ bl,
    const float* __restrict__ Wr, float* __restrict__ out)
{
    extern __shared__ float sm[];
    float* Wls = sm;                       // [128][PITCH], Wls[k][n] = Wl[n][k]
    float* Wrs = sm + 128 * PITCH;
    float* xs  = sm + 2 * 128 * PITCH;     // [128][128], row-swizzled

    const int tid = threadIdx.x;
    // Stage both weight matrices transposed (coalesced gmem reads)
    for (int idx = tid; idx < 128 * 32; idx += 256) {
        int n = idx >> 5;
        int k4 = (idx & 31) << 2;
        float4 a = *(const float4*)(Wl + n * 128 + k4);
        Wls[(k4 + 0) * PITCH + n] = a.x; Wls[(k4 + 1) * PITCH + n] = a.y;
        Wls[(k4 + 2) * PITCH + n] = a.z; Wls[(k4 + 3) * PITCH + n] = a.w;
        float4 b = *(const float4*)(Wr + n * 128 + k4);
        Wrs[(k4 + 0) * PITCH + n] = b.x; Wrs[(k4 + 1) * PITCH + n] = b.y;
        Wrs[(k4 + 2) * PITCH + n] = b.z; Wrs[(k4 + 3) * PITCH + n] = b.w;
    }

    const int wrp  = tid >> 5;
    const int lane = tid & 31;
    const int lc   = lane & 15;            // 16 col positions
    const int lr   = lane >> 4;            // 2 row groups
    const int rloc = wrp * 16 + lr * 8;    // local row base (multiple of 8)
    const int row0 = blockIdx.x * GEMM_ROWS;
    const int c0   = lc * 4;
    const int sw   = ((rloc >> 3) & 1) << 2;   // xor-4 swizzle for this thread's rows

    float4 b0 = *(const float4*)(bl + c0);
    float4 b1 = *(const float4*)(bl + 64 + c0);
    ull acc[8][4];
    #pragma unroll
    for (int i = 0; i < 8; i++) {
        acc[i][0] = pk2(b0.x, b0.y); acc[i][1] = pk2(b0.z, b0.w);
        acc[i][2] = pk2(b1.x, b1.y); acc[i][3] = pk2(b1.z, b1.w);
    }

    #pragma unroll
    for (int ph = 0; ph < 2; ph++) {
        const float* src = ph ? hin : mean;
        const float* Ws  = ph ? Wrs : Wls;
        __syncthreads();   // weights staged (ph0) / previous xs consumed (ph1)
        for (int idx = tid; idx < GEMM_ROWS * 32; idx += 256) {
            int r = idx >> 5;
            int k4 = (idx & 31) << 2;
            int gr = row0 + r;
            float4 v = make_float4(0.f, 0.f, 0.f, 0.f);
            if (gr < NN) v = *(const float4*)(src + gr * 128 + k4);
            *(float4*)(xs + r * 128 + (k4 ^ (((r >> 3) & 1) << 2))) = v;
        }
        __syncthreads();
        #pragma unroll 2
        for (int kk = 0; kk < 128; kk += 4) {
            float4 xv[8];
            #pragma unroll
            for (int i = 0; i < 8; i++)
                xv[i] = *(const float4*)(xs + (rloc + i) * 128 + (kk ^ sw));
            #pragma unroll
            for (int k = 0; k < 4; k++) {
                const float* wr_ = Ws + (kk + k) * PITCH;
                float4 wa = *(const float4*)(wr_ + c0);
                float4 wb = *(const float4*)(wr_ + 64 + c0);
                ull w01 = pk2(wa.x, wa.y), w23 = pk2(wa.z, wa.w);
                ull w45 = pk2(wb.x, wb.y), w67 = pk2(wb.z, wb.w);
                #pragma unroll
                for (int i = 0; i < 8; i++) {
                    float xk = ((const float*)&xv[i])[k];
                    ull xx = pk2(xk, xk);
                    fma2(acc[i][0], w01, xx);
                    fma2(acc[i][1], w23, xx);
                    fma2(acc[i][2], w45, xx);
                    fma2(acc[i][3], w67, xx);
                }
            }
        }
    }

    #pragma unroll
    for (int i = 0; i < 8; i++) {
        int gr = row0 + rloc + i;
        if (gr < NN) {
            float a, b, c, d, e, f, g, h;
            upk2(acc[i][0], a, b); upk2(acc[i][1], c, d);
            upk2(acc[i][2], e, f); upk2(acc[i][3], g, h);
            *(float4*)(out + gr * 128 + c0) =
                make_float4(fmaxf(a, 0.f), fmaxf(b, 0.f), fmaxf(c, 0.f), fmaxf(d, 0.f));
            *(float4*)(out + gr * 128 + 64 + c0) =
                make_float4(fmaxf(e, 0.f), fmaxf(f, 0.f), fmaxf(g, 0.f), fmaxf(h, 0.f));
        }
    }
}

// ---------------- launch ----------------
extern "C" void kernel_launch(void* const* d_in, const int* in_sizes, int n_in,
                              void* d_out, int out_size) {
    const float* x   = (const float*)d_in[0];
    const void*  ei  = d_in[1];
    const float* Wl1 = (const float*)d_in[2];
    const float* bl1 = (const float*)d_in[3];
    const float* Wr1 = (const float*)d_in[4];
    const float* Wl2 = (const float*)d_in[5];
    const float* bl2 = (const float*)d_in[6];
    const float* Wr2 = (const float*)d_in[7];
    const float* Wl3 = (const float*)d_in[8];
    const float* bl3 = (const float*)d_in[9];
    const float* Wr3 = (const float*)d_in[10];
    float* out = (float*)d_out;

    cudaFuncSetAttribute(gemm_kernel, cudaFuncAttributeMaxDynamicSharedMemorySize, GEMM_SMEM);

    float *pA, *pB, *pM;
    cudaGetSymbolAddress((void**)&pA, g_bufA);
    cudaGetSymbolAddress((void**)&pB, g_bufB);
    cudaGetSymbolAddress((void**)&pM, g_mean);

    // ---- graph preprocessing (identical every call: deterministic) ----
    init_kernel<<<(NN + 255) / 256, 256>>>((const unsigned long long*)ei);
    convert_hist_kernel<<<(EE + 255) / 256, 256>>>(ei);
    scan_kernel<<<1, 1024>>>();
    fill_kernel<<<(EE + 255) / 256, 256>>>();
    sortnb_kernel<<<(NN + 127) / 128, 128>>>();

    const int agg_blocks  = (NN * 32 + 255) / 256;        // one warp per node
    const int gemm_blocks = (NN + GEMM_ROWS - 1) / GEMM_ROWS;

    // ---- layer 1 ----
    aggregate_kernel<<<agg_blocks, 256>>>(x, pM);
    gemm_kernel<<<gemm_blocks, 256, GEMM_SMEM>>>(pM, x, Wl1, bl1, Wr1, pA);
    // ---- layer 2 ----
    aggregate_kernel<<<agg_blocks, 256>>>(pA, pM);
    gemm_kernel<<<gemm_blocks, 256, GEMM_SMEM>>>(pM, pA, Wl2, bl2, Wr2, pB);
    // ---- layer 3 ----
    aggregate_kernel<<<agg_blocks, 256>>>(pB, pM);
    gemm_kernel<<<gemm_blocks, 256, GEMM_SMEM>>>(pM, pB, Wl3, bl3, Wr3, out);
}

// round 5
// speedup vs baseline: 2.1116x; 1.7712x over previous
#include <cuda_runtime.h>
#include <cuda_bf16.h>

#define NN 50000
#define EE 600000
#define DD 128
#define NTILES 391            // ceil(NN/128)
#define GRID_GEMM 148

// ---- gemm smem layout (bytes) ----
// W hi: [128 n][256 k] bf16 = 64KB ; W lo: 64KB ; A: 2 bufs x (hi 16KB + lo 16KB)
#define SM_WH 0
#define SM_WL 65536
#define SM_AB 131072
#define GEMM_SMEM (131072 + 2*32768)   // 196608

// swizzles: XOR row%8 into the 16B-chunk index (conflict-free ldmatrix)
#define SWA(o) ((o) ^ ((((unsigned)(o)) >> 3) & 0x70))   // 128B rows (A tiles)
#define SWW(o) ((o) ^ ((((unsigned)(o)) >> 5) & 0x70))   // 512B rows (W tiles)

typedef unsigned int u32;

// ---------------- scratch ----------------
__device__ float g_bufA[NN * DD];
__device__ float g_bufB[NN * DD];
__device__ float g_mean[NN * DD];
__device__ int   g_src[EE];
__device__ int   g_dst[EE];
__device__ int   g_col[EE];
__device__ int   g_rowptr[NN + 1];
__device__ int   g_cursor[NN];
__device__ int   g_count[NN];
__device__ float g_invdeg[NN];
__device__ int   g_is64;

// ---------------- helpers ----------------
__device__ __forceinline__ u32 smem_u32(const void* p) {
    u32 a;
    asm("{ .reg .u64 t; cvta.to.shared.u64 t, %1; cvt.u32.u64 %0, t; }" : "=r"(a) : "l"(p));
    return a;
}
__device__ __forceinline__ void ldm4(u32& r0, u32& r1, u32& r2, u32& r3, u32 a) {
    asm volatile("ldmatrix.sync.aligned.m8n8.x4.shared.b16 {%0,%1,%2,%3}, [%4];"
                 : "=r"(r0), "=r"(r1), "=r"(r2), "=r"(r3) : "r"(a));
}
__device__ __forceinline__ void mma_bf16(float* d, const u32* a, u32 b0, u32 b1) {
    asm volatile(
        "mma.sync.aligned.m16n8k16.row.col.f32.bf16.bf16.f32 "
        "{%0,%1,%2,%3}, {%4,%5,%6,%7}, {%8,%9}, {%0,%1,%2,%3};"
        : "+f"(d[0]), "+f"(d[1]), "+f"(d[2]), "+f"(d[3])
        : "r"(a[0]), "r"(a[1]), "r"(a[2]), "r"(a[3]), "r"(b0), "r"(b1));
}
__device__ __forceinline__ u32 pkbf2(float x, float y) {
    __nv_bfloat162 h = __floats2bfloat162_rn(x, y);
    return *(u32*)&h;
}
// split float4 -> packed hi (2x u32) and lo (2x u32)
__device__ __forceinline__ void split4(float4 v, uint2& h, uint2& l) {
    float bx = __bfloat162float(__float2bfloat16_rn(v.x));
    float by = __bfloat162float(__float2bfloat16_rn(v.y));
    float bz = __bfloat162float(__float2bfloat16_rn(v.z));
    float bw = __bfloat162float(__float2bfloat16_rn(v.w));
    h.x = pkbf2(v.x, v.y);          h.y = pkbf2(v.z, v.w);
    l.x = pkbf2(v.x - bx, v.y - by); l.y = pkbf2(v.z - bz, v.w - bw);
}

// ---------------- preprocessing (unchanged) ----------------
__global__ void init_kernel(const unsigned long long* __restrict__ e) {
    int i = blockIdx.x * blockDim.x + threadIdx.x;
    if (i < NN) g_count[i] = 0;
    if (i == 0) {
        int ok = 1;
        #pragma unroll
        for (int t = 0; t < 8; t++)
            if (e[t] >= (unsigned long long)NN) ok = 0;
        g_is64 = ok;
    }
}

__global__ void convert_hist_kernel(const void* __restrict__ eptr) {
    int i = blockIdx.x * blockDim.x + threadIdx.x;
    if (i >= EE) return;
    int s, d;
    if (g_is64) {
        const long long* e = (const long long*)eptr;
        s = (int)e[i]; d = (int)e[EE + i];
    } else {
        const int* e = (const int*)eptr;
        s = e[i]; d = e[EE + i];
    }
    g_src[i] = s;
    g_dst[i] = d;
    atomicAdd(&g_count[d], 1);
}

__global__ void scan_kernel() {
    __shared__ int wsum[32];
    __shared__ int carry_s;
    int tid = threadIdx.x;
    int lane = tid & 31, wid = tid >> 5;
    if (tid == 0) carry_s = 0;
    __syncthreads();
    for (int base = 0; base < NN; base += 1024) {
        int idx = base + tid;
        int v = (idx < NN) ? g_count[idx] : 0;
        int s = v;
        #pragma unroll
        for (int o = 1; o < 32; o <<= 1) {
            int t = __shfl_up_sync(0xffffffffu, s, o);
            if (lane >= o) s += t;
        }
        if (lane == 31) wsum[wid] = s;
        __syncthreads();
        if (wid == 0) {
            int w = wsum[lane];
            #pragma unroll
            for (int o = 1; o < 32; o <<= 1) {
                int t = __shfl_up_sync(0xffffffffu, w, o);
                if (lane >= o) w += t;
            }
            wsum[lane] = w;
        }
        __syncthreads();
        int offset = ((wid > 0) ? wsum[wid - 1] : 0) + carry_s;
        int incl = s + offset;
        if (idx < NN) {
            int excl = incl - v;
            g_rowptr[idx] = excl;
            g_cursor[idx] = excl;
            g_invdeg[idx] = 1.0f / (float)max(v, 1);
        }
        __syncthreads();
        if (tid == 1023) carry_s = incl;
        __syncthreads();
    }
    if (tid == 0) g_rowptr[NN] = carry_s;
}

__global__ void fill_kernel() {
    int i = blockIdx.x * blockDim.x + threadIdx.x;
    if (i >= EE) return;
    int d = g_dst[i];
    int p = atomicAdd(&g_cursor[d], 1);
    g_col[p] = g_src[i];
}

__global__ void sortnb_kernel() {
    int n = blockIdx.x * blockDim.x + threadIdx.x;
    if (n >= NN) return;
    int b = g_rowptr[n], e = g_rowptr[n + 1];
    for (int i = b; i < e - 1; i++) {
        int m = i, vm = g_col[i];
        for (int j = i + 1; j < e; j++) {
            int vj = g_col[j];
            if (vj < vm) { m = j; vm = vj; }
        }
        if (m != i) { g_col[m] = g_col[i]; g_col[i] = vm; }
    }
}

// ---------------- aggregation (unchanged) ----------------
__global__ void aggregate_kernel(const float* __restrict__ hin, float* __restrict__ mean) {
    int node = (blockIdx.x * blockDim.x + threadIdx.x) >> 5;
    if (node >= NN) return;
    int lane = threadIdx.x & 31;
    int j = g_rowptr[node], end = g_rowptr[node + 1];
    const float4* p = (const float4*)hin;
    float4 acc = make_float4(0.f, 0.f, 0.f, 0.f);
    for (; j + 2 <= end; j += 2) {
        int s0 = g_col[j], s1 = g_col[j + 1];
        float4 v0 = p[s0 * 32 + lane];
        float4 v1 = p[s1 * 32 + lane];
        acc.x += v0.x; acc.y += v0.y; acc.z += v0.z; acc.w += v0.w;
        acc.x += v1.x; acc.y += v1.y; acc.z += v1.z; acc.w += v1.w;
    }
    if (j < end) {
        float4 v = p[g_col[j] * 32 + lane];
        acc.x += v.x; acc.y += v.y; acc.z += v.z; acc.w += v.w;
    }
    float id = g_invdeg[node];
    acc.x *= id; acc.y *= id; acc.z *= id; acc.w *= id;
    *((float4*)mean + node * 32 + lane) = acc;
}

// ---------------- bf16x3 mma.sync GEMM ----------------
// out = relu([mean|h] @ [Wl;Wr]^T + bl) as one K=256 GEMM.
// 148 persistent CTAs x 256 thr (8 warps); warp tile 64x32 (4 m-frags x 4 n-frags).
// W hi/lo staged once in smem; A chunks (128 rows x 64 k) double-buffered,
// gmem loads issued before the mma block to hide L2 latency.
__global__ __launch_bounds__(256, 1)
void gemm_mma_kernel(const float* __restrict__ mean, const float* __restrict__ hin,
                     const float* __restrict__ Wl, const float* __restrict__ bl,
                     const float* __restrict__ Wr, float* __restrict__ out)
{
    extern __shared__ char smem[];
    const u32 sb = smem_u32(smem);
    const int tid = threadIdx.x;
    const int w = tid >> 5;
    const int lane = tid & 31;

    // ---- stage W hi/lo: Wcat[n][k] (k<128: Wl, else Wr), rows 512B, SWW swizzle ----
    for (int s = tid; s < 128 * 64; s += 256) {
        int n = s >> 6, k4 = s & 63;
        int k = k4 * 4;
        float4 v = (k < 128) ? *(const float4*)(Wl + n * 128 + k)
                             : *(const float4*)(Wr + n * 128 + (k - 128));
        uint2 h, l;
        split4(v, h, l);
        u32 off = SWW(n * 512 + k4 * 8);
        *(uint2*)(smem + SM_WH + off) = h;
        *(uint2*)(smem + SM_WL + off) = l;
    }

    // per-thread ldmatrix lane offsets
    const int wr = (w & 1) * 64;           // warp row base in tile
    const int wc = (w >> 1) * 32;          // warp col base
    const u32 a_lane = (u32)((lane & 15) * 128 + ((lane >> 4) & 1) * 16);
    const u32 b_lane = (u32)(((lane & 7) + ((lane >> 4) & 1) * 8) * 512 + ((lane >> 3) & 1) * 16);

    // bias regs for this thread's columns
    float2 brg[4];
    #pragma unroll
    for (int ni = 0; ni < 4; ni++)
        brg[ni] = *(const float2*)(bl + wc + ni * 8 + (lane & 3) * 2);

    __syncthreads();

    for (int tix = blockIdx.x; tix < NTILES; tix += GRID_GEMM) {
        const int row0 = tix * 128;
        float acc[16][4];
        #pragma unroll
        for (int i = 0; i < 16; i++)
            #pragma unroll
            for (int q = 0; q < 4; q++) acc[i][q] = 0.f;

        // stage chunk 0 into buf 0
        float4 v[8];
        {
            const float* src = mean;
            #pragma unroll
            for (int j = 0; j < 8; j++) {
                int s = tid + j * 256;
                int row = s >> 4, k4 = s & 15;
                int gr = row0 + row;
                v[j] = make_float4(0.f, 0.f, 0.f, 0.f);
                if (gr < NN) v[j] = *(const float4*)(src + gr * 128 + k4 * 4);
            }
            #pragma unroll
            for (int j = 0; j < 8; j++) {
                int s = tid + j * 256;
                int row = s >> 4, k4 = s & 15;
                uint2 h, l;
                split4(v[j], h, l);
                u32 off = SWA(row * 128 + k4 * 8);
                *(uint2*)(smem + SM_AB + off) = h;
                *(uint2*)(smem + SM_AB + 16384 + off) = l;
            }
        }
        __syncthreads();

        for (int kc = 0; kc < 4; kc++) {
            const int buf = kc & 1;

            // prefetch next chunk's gmem into regs (hidden behind mma)
            if (kc < 3) {
                const float* src = (kc + 1 < 2) ? mean : hin;
                int kbase = ((kc + 1) & 1) * 64;
                #pragma unroll
                for (int j = 0; j < 8; j++) {
                    int s = tid + j * 256;
                    int row = s >> 4, k4 = s & 15;
                    int gr = row0 + row;
                    v[j] = make_float4(0.f, 0.f, 0.f, 0.f);
                    if (gr < NN) v[j] = *(const float4*)(src + gr * 128 + kbase + k4 * 4);
                }
            }

            // ---- mma over 4 k16 steps, 3 split terms ----
            const u32 AH = sb + SM_AB + buf * 32768;
            const u32 AL = AH + 16384;
            const u32 BH = sb + SM_WH;
            const u32 BL = sb + SM_WL;
            #pragma unroll
            for (int ks = 0; ks < 4; ks++) {
                u32 ah[4][4], al[4][4], bh[2][4], blr[2][4];
                u32 aoff = (u32)(wr * 128) + (u32)(ks * 32) + a_lane;
                #pragma unroll
                for (int mi = 0; mi < 4; mi++)
                    ldm4(ah[mi][0], ah[mi][1], ah[mi][2], ah[mi][3],
                         AH + SWA(aoff + mi * 16 * 128));
                u32 boff = (u32)(wc * 512) + (u32)((kc * 8 + ks * 2) * 16) + b_lane;
                #pragma unroll
                for (int g = 0; g < 2; g++)
                    ldm4(bh[g][0], bh[g][1], bh[g][2], bh[g][3],
                         BH + SWW(boff + g * 16 * 512));
                // hi*hi
                #pragma unroll
                for (int mi = 0; mi < 4; mi++)
                    #pragma unroll
                    for (int ni = 0; ni < 4; ni++)
                        mma_bf16(acc[mi * 4 + ni], ah[mi],
                                 bh[ni >> 1][(ni & 1) * 2], bh[ni >> 1][(ni & 1) * 2 + 1]);
                // hi*lo
                #pragma unroll
                for (int g = 0; g < 2; g++)
                    ldm4(blr[g][0], blr[g][1], blr[g][2], blr[g][3],
                         BL + SWW(boff + g * 16 * 512));
                #pragma unroll
                for (int mi = 0; mi < 4; mi++)
                    #pragma unroll
                    for (int ni = 0; ni < 4; ni++)
                        mma_bf16(acc[mi * 4 + ni], ah[mi],
                                 blr[ni >> 1][(ni & 1) * 2], blr[ni >> 1][(ni & 1) * 2 + 1]);
                // lo*hi
                #pragma unroll
                for (int mi = 0; mi < 4; mi++)
                    ldm4(al[mi][0], al[mi][1], al[mi][2], al[mi][3],
                         AL + SWA(aoff + mi * 16 * 128));
                #pragma unroll
                for (int mi = 0; mi < 4; mi++)
                    #pragma unroll
                    for (int ni = 0; ni < 4; ni++)
                        mma_bf16(acc[mi * 4 + ni], al[mi],
                                 bh[ni >> 1][(ni & 1) * 2], bh[ni >> 1][(ni & 1) * 2 + 1]);
            }

            // store prefetched chunk into other buffer
            if (kc < 3) {
                int nb = buf ^ 1;
                #pragma unroll
                for (int j = 0; j < 8; j++) {
                    int s = tid + j * 256;
                    int row = s >> 4, k4 = s & 15;
                    uint2 h, l;
                    split4(v[j], h, l);
                    u32 off = SWA(row * 128 + k4 * 8);
                    *(uint2*)(smem + SM_AB + nb * 32768 + off) = h;
                    *(uint2*)(smem + SM_AB + nb * 32768 + 16384 + off) = l;
                }
            }
            __syncthreads();
        }

        // ---- epilogue: bias + relu + direct STG ----
        #pragma unroll
        for (int mi = 0; mi < 4; mi++) {
            int r0 = row0 + wr + mi * 16 + (lane >> 2);
            #pragma unroll
            for (int ni = 0; ni < 4; ni++) {
                const float* d = acc[mi * 4 + ni];
                int c = wc + ni * 8 + (lane & 3) * 2;
                if (r0 < NN) {
                    float2 o;
                    o.x = fmaxf(d[0] + brg[ni].x, 0.f);
                    o.y = fmaxf(d[1] + brg[ni].y, 0.f);
                    *(float2*)(out + (long)r0 * 128 + c) = o;
                }
                if (r0 + 8 < NN) {
                    float2 o;
                    o.x = fmaxf(d[2] + brg[ni].x, 0.f);
                    o.y = fmaxf(d[3] + brg[ni].y, 0.f);
                    *(float2*)(out + (long)(r0 + 8) * 128 + c) = o;
                }
            }
        }
        __syncthreads();   // tile done before next chunk0 staging overwrites buf0
    }
}

// ---------------- launch ----------------
extern "C" void kernel_launch(void* const* d_in, const int* in_sizes, int n_in,
                              void* d_out, int out_size) {
    const float* x   = (const float*)d_in[0];
    const void*  ei  = d_in[1];
    const float* Wl1 = (const float*)d_in[2];
    const float* bl1 = (const float*)d_in[3];
    const float* Wr1 = (const float*)d_in[4];
    const float* Wl2 = (const float*)d_in[5];
    const float* bl2 = (const float*)d_in[6];
    const float* Wr2 = (const float*)d_in[7];
    const float* Wl3 = (const float*)d_in[8];
    const float* bl3 = (const float*)d_in[9];
    const float* Wr3 = (const float*)d_in[10];
    float* out = (float*)d_out;

    cudaFuncSetAttribute(gemm_mma_kernel, cudaFuncAttributeMaxDynamicSharedMemorySize, GEMM_SMEM);

    float *pA, *pB, *pM;
    cudaGetSymbolAddress((void**)&pA, g_bufA);
    cudaGetSymbolAddress((void**)&pB, g_bufB);
    cudaGetSymbolAddress((void**)&pM, g_mean);

    // ---- graph preprocessing (deterministic every call) ----
    init_kernel<<<(NN + 255) / 256, 256>>>((const unsigned long long*)ei);
    convert_hist_kernel<<<(EE + 255) / 256, 256>>>(ei);
    scan_kernel<<<1, 1024>>>();
    fill_kernel<<<(EE + 255) / 256, 256>>>();
    sortnb_kernel<<<(NN + 127) / 128, 128>>>();

    const int agg_blocks = (NN * 32 + 255) / 256;

    // ---- layer 1 ----
    aggregate_kernel<<<agg_blocks, 256>>>(x, pM);
    gemm_mma_kernel<<<GRID_GEMM, 256, GEMM_SMEM>>>(pM, x, Wl1, bl1, Wr1, pA);
    // ---- layer 2 ----
    aggregate_kernel<<<agg_blocks, 256>>>(pA, pM);
    gemm_mma_kernel<<<GRID_GEMM, 256, GEMM_SMEM>>>(pM, pA, Wl2, bl2, Wr2, pB);
    // ---- layer 3 ----
    aggregate_kernel<<<agg_blocks, 256>>>(pB, pM);
    gemm_mma_kernel<<<GRID_GEMM, 256, GEMM_SMEM>>>(pM, pB, Wl3, bl3, Wr3, out);
}